// round 2
// baseline (speedup 1.0000x reference)
#include <cuda_runtime.h>
#include <math.h>

#define BB 4
#define LQ 2048
#define LK 2048
#define DM 1024
#define NH 16
#define DK 64
#define NEGV -1000000000.0f

// Projected q/k/v scratch: [B, LEN, H*DK] row-major.
__device__ float g_q[BB * LQ * NH * DK];
__device__ float g_k[BB * LK * NH * DK];
__device__ float g_v[BB * LK * NH * DK];

// ---------------------------------------------------------------------------
// tf32 helpers: split fp32 x into hi + lo, both exactly representable in tf32.
// Dropped term (lo_residual) is ~2^-21 * |x| -> near-fp32 accuracy with 3 MMAs.
// ---------------------------------------------------------------------------
__device__ __forceinline__ void split_tf32(float x, float& h, float& l) {
    h = __uint_as_float(__float_as_uint(x) & 0xFFFFE000u);
    float r = x - h;
    l = __uint_as_float(__float_as_uint(r) & 0xFFFFE000u);
}

// mma.sync m16n8k8 tf32: D = A*B + C (C=D in place).
// A frag: a0=(g,tg) a1=(g+8,tg) a2=(g,tg+4) a3=(g+8,tg+4)   [g=lane/4, tg=lane%4]
// B frag: b0=(k=tg,n=g) b1=(k=tg+4,n=g)
// C frag: c0=(g,2tg) c1=(g,2tg+1) c2=(g+8,2tg) c3=(g+8,2tg+1)
__device__ __forceinline__ void mma8(float c[4], const unsigned a[4], const unsigned b[2]) {
    asm volatile(
        "mma.sync.aligned.m16n8k8.row.col.f32.tf32.tf32.f32 "
        "{%0,%1,%2,%3}, {%4,%5,%6,%7}, {%8,%9}, {%0,%1,%2,%3};\n"
        : "+f"(c[0]), "+f"(c[1]), "+f"(c[2]), "+f"(c[3])
        : "r"(a[0]), "r"(a[1]), "r"(a[2]), "r"(a[3]), "r"(b[0]), "r"(b[1]));
}

// ---------------------------------------------------------------------------
// Projection GEMM: C[m][n] = sum_k A[m][k]*W[n][k] (+bias[n]), 3xTF32.
// Block tile 128(M) x 64(N), BK=16, 256 threads = 8 warps (4m x 2n),
// warp tile 32x32 = 2 m16 frags x 4 n8 frags.
// ---------------------------------------------------------------------------
#define PBM 128
#define PBN 64
#define PBK 16

__global__ __launch_bounds__(256) void proj_mma(
    const float* __restrict__ A, const float* __restrict__ W,
    const float* __restrict__ bias, float* __restrict__ C,
    int M, int N, int K)
{
    __shared__ float Ah[PBM][PBK + 1], Al[PBM][PBK + 1];
    __shared__ float Wh[PBN][PBK + 1], Wl[PBN][PBK + 1];

    const int tid  = threadIdx.x;
    const int warp = tid >> 5, lane = tid & 31;
    const int g = lane >> 2, tg = lane & 3;
    const int wm = warp >> 1, wn = warp & 1;
    const int bm = blockIdx.y * PBM, bn = blockIdx.x * PBN;

    float acc[2][4][4];
#pragma unroll
    for (int i = 0; i < 2; ++i)
#pragma unroll
        for (int j = 0; j < 4; ++j)
#pragma unroll
            for (int t = 0; t < 4; ++t) acc[i][j][t] = 0.f;

    for (int k0 = 0; k0 < K; k0 += PBK) {
        // Stage A tile: 128x16 floats = 512 float4, 2 per thread.
#pragma unroll
        for (int i = 0; i < 2; ++i) {
            int f4 = tid + i * 256;
            int r = f4 >> 2, c4 = (f4 & 3) * 4;
            float4 v = *(const float4*)(A + (size_t)(bm + r) * K + k0 + c4);
            float h, l;
            split_tf32(v.x, h, l); Ah[r][c4 + 0] = h; Al[r][c4 + 0] = l;
            split_tf32(v.y, h, l); Ah[r][c4 + 1] = h; Al[r][c4 + 1] = l;
            split_tf32(v.z, h, l); Ah[r][c4 + 2] = h; Al[r][c4 + 2] = l;
            split_tf32(v.w, h, l); Ah[r][c4 + 3] = h; Al[r][c4 + 3] = l;
        }
        // Stage W tile: 64x16 = 256 float4, 1 per thread.
        {
            int r = tid >> 2, c4 = (tid & 3) * 4;
            float4 v = *(const float4*)(W + (size_t)(bn + r) * K + k0 + c4);
            float h, l;
            split_tf32(v.x, h, l); Wh[r][c4 + 0] = h; Wl[r][c4 + 0] = l;
            split_tf32(v.y, h, l); Wh[r][c4 + 1] = h; Wl[r][c4 + 1] = l;
            split_tf32(v.z, h, l); Wh[r][c4 + 2] = h; Wl[r][c4 + 2] = l;
            split_tf32(v.w, h, l); Wh[r][c4 + 3] = h; Wl[r][c4 + 3] = l;
        }
        __syncthreads();

#pragma unroll
        for (int kk = 0; kk < PBK; kk += 8) {
            unsigned ah[2][4], al[2][4], bh[4][2], bl[4][2];
#pragma unroll
            for (int mf = 0; mf < 2; ++mf) {
                int r0 = wm * 32 + mf * 16;
                ah[mf][0] = __float_as_uint(Ah[r0 + g    ][kk + tg    ]);
                ah[mf][1] = __float_as_uint(Ah[r0 + g + 8][kk + tg    ]);
                ah[mf][2] = __float_as_uint(Ah[r0 + g    ][kk + tg + 4]);
                ah[mf][3] = __float_as_uint(Ah[r0 + g + 8][kk + tg + 4]);
                al[mf][0] = __float_as_uint(Al[r0 + g    ][kk + tg    ]);
                al[mf][1] = __float_as_uint(Al[r0 + g + 8][kk + tg    ]);
                al[mf][2] = __float_as_uint(Al[r0 + g    ][kk + tg + 4]);
                al[mf][3] = __float_as_uint(Al[r0 + g + 8][kk + tg + 4]);
            }
#pragma unroll
            for (int nf = 0; nf < 4; ++nf) {
                int n0 = wn * 32 + nf * 8;
                bh[nf][0] = __float_as_uint(Wh[n0 + g][kk + tg    ]);
                bh[nf][1] = __float_as_uint(Wh[n0 + g][kk + tg + 4]);
                bl[nf][0] = __float_as_uint(Wl[n0 + g][kk + tg    ]);
                bl[nf][1] = __float_as_uint(Wl[n0 + g][kk + tg + 4]);
            }
#pragma unroll
            for (int mf = 0; mf < 2; ++mf)
#pragma unroll
                for (int nf = 0; nf < 4; ++nf) {
                    mma8(acc[mf][nf], ah[mf], bh[nf]);
                    mma8(acc[mf][nf], ah[mf], bl[nf]);
                    mma8(acc[mf][nf], al[mf], bh[nf]);
                }
        }
        __syncthreads();
    }

    // Epilogue: bias + store (float2 per row-pair entry).
#pragma unroll
    for (int mf = 0; mf < 2; ++mf) {
#pragma unroll
        for (int nf = 0; nf < 4; ++nf) {
            int r = bm + wm * 32 + mf * 16 + g;
            int c = bn + wn * 32 + nf * 8 + 2 * tg;
            float b0 = bias ? bias[c] : 0.f;
            float b1 = bias ? bias[c + 1] : 0.f;
            *(float2*)(C + (size_t)r * N + c) =
                make_float2(acc[mf][nf][0] + b0, acc[mf][nf][1] + b1);
            *(float2*)(C + (size_t)(r + 8) * N + c) =
                make_float2(acc[mf][nf][2] + b0, acc[mf][nf][3] + b1);
        }
    }
}

// ---------------------------------------------------------------------------
// Flash attention with mma.sync tf32 (3xTF32 everywhere).
// Block = 64 queries of one (b,h); KV tiles of 32; online softmax.
// 8 warps: wm=warp/2 (16-row stripe), wn=warp%2.
//   S tile 64x32: warp tile 16x16 (2 n8 frags). O tile 64x64: warp 16x32 (4 n8).
// ---------------------------------------------------------------------------
struct AttnSmem {
    float qh[64][65]; float ql[64][65];
    float kh[32][65]; float kl[32][65];
    float vth[64][33]; float vtl[64][33];   // transposed V: [d][key]
    float ph[64][33]; float pl[64][33];     // raw scores, then P hi/lo
    float m_s[64]; float l_s[64]; float al_s[64];
    int msk[32];
};

__global__ __launch_bounds__(256) void attn_mma(
    const float* __restrict__ q, const float* __restrict__ k,
    const float* __restrict__ v, const int* __restrict__ mask,
    float* __restrict__ out)
{
    extern __shared__ char smem_raw[];
    AttnSmem& S = *reinterpret_cast<AttnSmem*>(smem_raw);

    const int tid  = threadIdx.x;
    const int warp = tid >> 5, lane = tid & 31;
    const int g = lane >> 2, tg = lane & 3;
    const int wm = warp >> 1, wn = warp & 1;
    const int b = blockIdx.z, h = blockIdx.y;
    const int q0 = blockIdx.x * 64;

    // Load Q tile 64x64 (16 floats/thread, float4).
#pragma unroll
    for (int i = 0; i < 4; ++i) {
        int f4 = tid + i * 256;
        int r = f4 >> 4, c4 = (f4 & 15) * 4;
        float4 val = *(const float4*)(q + ((size_t)(b * LQ + q0 + r) * NH + h) * DK + c4);
        float hh, ll;
        split_tf32(val.x, hh, ll); S.qh[r][c4 + 0] = hh; S.ql[r][c4 + 0] = ll;
        split_tf32(val.y, hh, ll); S.qh[r][c4 + 1] = hh; S.ql[r][c4 + 1] = ll;
        split_tf32(val.z, hh, ll); S.qh[r][c4 + 2] = hh; S.ql[r][c4 + 2] = ll;
        split_tf32(val.w, hh, ll); S.qh[r][c4 + 3] = hh; S.ql[r][c4 + 3] = ll;
    }
    if (tid < 64) { S.m_s[tid] = -INFINITY; S.l_s[tid] = 0.f; }

    float o[4][4];
#pragma unroll
    for (int i = 0; i < 4; ++i)
#pragma unroll
        for (int j = 0; j < 4; ++j) o[i][j] = 0.f;

    for (int kt = 0; kt < LK; kt += 32) {
        __syncthreads();
        // Load K,V tiles (32x64 each), V transposed into vth.
#pragma unroll
        for (int i = 0; i < 2; ++i) {
            int f4 = tid + i * 256;
            int r = f4 >> 4, c4 = (f4 & 15) * 4;
            size_t gi = ((size_t)(b * LK + kt + r) * NH + h) * DK + c4;
            float4 kv = *(const float4*)(k + gi);
            float4 vv = *(const float4*)(v + gi);
            float hh, ll;
            split_tf32(kv.x, hh, ll); S.kh[r][c4 + 0] = hh; S.kl[r][c4 + 0] = ll;
            split_tf32(kv.y, hh, ll); S.kh[r][c4 + 1] = hh; S.kl[r][c4 + 1] = ll;
            split_tf32(kv.z, hh, ll); S.kh[r][c4 + 2] = hh; S.kl[r][c4 + 2] = ll;
            split_tf32(kv.w, hh, ll); S.kh[r][c4 + 3] = hh; S.kl[r][c4 + 3] = ll;
            split_tf32(vv.x, hh, ll); S.vth[c4 + 0][r] = hh; S.vtl[c4 + 0][r] = ll;
            split_tf32(vv.y, hh, ll); S.vth[c4 + 1][r] = hh; S.vtl[c4 + 1][r] = ll;
            split_tf32(vv.z, hh, ll); S.vth[c4 + 2][r] = hh; S.vtl[c4 + 2][r] = ll;
            split_tf32(vv.w, hh, ll); S.vth[c4 + 3][r] = hh; S.vtl[c4 + 3][r] = ll;
        }
        if (tid < 32) S.msk[tid] = mask[b * LK + kt + tid];
        __syncthreads();

        // ---- S = Q K^T (64x32), 3xTF32 ----
        float sacc[2][4];
#pragma unroll
        for (int nf = 0; nf < 2; ++nf)
#pragma unroll
            for (int t = 0; t < 4; ++t) sacc[nf][t] = 0.f;

#pragma unroll
        for (int kk = 0; kk < 64; kk += 8) {
            unsigned ah[4], al[4], bh[2][2], bl[2][2];
            int r0 = wm * 16;
            ah[0] = __float_as_uint(S.qh[r0 + g    ][kk + tg    ]);
            ah[1] = __float_as_uint(S.qh[r0 + g + 8][kk + tg    ]);
            ah[2] = __float_as_uint(S.qh[r0 + g    ][kk + tg + 4]);
            ah[3] = __float_as_uint(S.qh[r0 + g + 8][kk + tg + 4]);
            al[0] = __float_as_uint(S.ql[r0 + g    ][kk + tg    ]);
            al[1] = __float_as_uint(S.ql[r0 + g + 8][kk + tg    ]);
            al[2] = __float_as_uint(S.ql[r0 + g    ][kk + tg + 4]);
            al[3] = __float_as_uint(S.ql[r0 + g + 8][kk + tg + 4]);
#pragma unroll
            for (int nf = 0; nf < 2; ++nf) {
                int n0 = wn * 16 + nf * 8;
                bh[nf][0] = __float_as_uint(S.kh[n0 + g][kk + tg    ]);
                bh[nf][1] = __float_as_uint(S.kh[n0 + g][kk + tg + 4]);
                bl[nf][0] = __float_as_uint(S.kl[n0 + g][kk + tg    ]);
                bl[nf][1] = __float_as_uint(S.kl[n0 + g][kk + tg + 4]);
            }
#pragma unroll
            for (int nf = 0; nf < 2; ++nf) {
                mma8(sacc[nf], ah, bh[nf]);
                mma8(sacc[nf], ah, bl[nf]);
                mma8(sacc[nf], al, bh[nf]);
            }
        }

        // Scale + mask, write raw scores to ph.
#pragma unroll
        for (int nf = 0; nf < 2; ++nf) {
            int n0 = wn * 16 + nf * 8 + 2 * tg;
            int r0 = wm * 16 + g;
            float s0 = sacc[nf][0] * 0.125f, s1 = sacc[nf][1] * 0.125f;
            float s2 = sacc[nf][2] * 0.125f, s3 = sacc[nf][3] * 0.125f;
            if (S.msk[n0] == 0)     { s0 = NEGV; s2 = NEGV; }
            if (S.msk[n0 + 1] == 0) { s1 = NEGV; s3 = NEGV; }
            S.ph[r0][n0] = s0;     S.ph[r0][n0 + 1] = s1;
            S.ph[r0 + 8][n0] = s2; S.ph[r0 + 8][n0 + 1] = s3;
        }
        __syncthreads();

        // ---- Online softmax: 4 threads per row, 8 cols each ----
        {
            int r = tid >> 2, sub = tid & 3;
            float mt = -INFINITY;
#pragma unroll
            for (int j = 0; j < 8; ++j) mt = fmaxf(mt, S.ph[r][sub * 8 + j]);
            mt = fmaxf(mt, __shfl_xor_sync(0xffffffffu, mt, 1));
            mt = fmaxf(mt, __shfl_xor_sync(0xffffffffu, mt, 2));
            float mo = S.m_s[r];
            float mn = fmaxf(mo, mt);
            float ls = 0.f;
#pragma unroll
            for (int j = 0; j < 8; ++j) {
                int c = sub * 8 + j;
                float p = __expf(S.ph[r][c] - mn);
                ls += p;
                float hh, ll;
                split_tf32(p, hh, ll);
                S.ph[r][c] = hh; S.pl[r][c] = ll;
            }
            ls += __shfl_xor_sync(0xffffffffu, ls, 1);
            ls += __shfl_xor_sync(0xffffffffu, ls, 2);
            if (sub == 0) {
                float alv = __expf(mo - mn);
                S.l_s[r] = S.l_s[r] * alv + ls;
                S.m_s[r] = mn;
                S.al_s[r] = alv;
            }
        }
        __syncthreads();

        // ---- O = O*alpha + P V (64x64), 3xTF32 ----
        {
            int r0 = wm * 16 + g;
            float a0 = S.al_s[r0], a1 = S.al_s[r0 + 8];
#pragma unroll
            for (int nf = 0; nf < 4; ++nf) {
                o[nf][0] *= a0; o[nf][1] *= a0;
                o[nf][2] *= a1; o[nf][3] *= a1;
            }
        }
#pragma unroll
        for (int kk = 0; kk < 32; kk += 8) {
            unsigned ah[4], al[4], bh[4][2], bl[4][2];
            int r0 = wm * 16;
            ah[0] = __float_as_uint(S.ph[r0 + g    ][kk + tg    ]);
            ah[1] = __float_as_uint(S.ph[r0 + g + 8][kk + tg    ]);
            ah[2] = __float_as_uint(S.ph[r0 + g    ][kk + tg + 4]);
            ah[3] = __float_as_uint(S.ph[r0 + g + 8][kk + tg + 4]);
            al[0] = __float_as_uint(S.pl[r0 + g    ][kk + tg    ]);
            al[1] = __float_as_uint(S.pl[r0 + g + 8][kk + tg    ]);
            al[2] = __float_as_uint(S.pl[r0 + g    ][kk + tg + 4]);
            al[3] = __float_as_uint(S.pl[r0 + g + 8][kk + tg + 4]);
#pragma unroll
            for (int nf = 0; nf < 4; ++nf) {
                int n0 = wn * 32 + nf * 8;
                bh[nf][0] = __float_as_uint(S.vth[n0 + g][kk + tg    ]);
                bh[nf][1] = __float_as_uint(S.vth[n0 + g][kk + tg + 4]);
                bl[nf][0] = __float_as_uint(S.vtl[n0 + g][kk + tg    ]);
                bl[nf][1] = __float_as_uint(S.vtl[n0 + g][kk + tg + 4]);
            }
#pragma unroll
            for (int nf = 0; nf < 4; ++nf) {
                mma8(o[nf], ah, bh[nf]);
                mma8(o[nf], ah, bl[nf]);
                mma8(o[nf], al, bh[nf]);
            }
        }
    }

    // Final normalize + store.
    {
        int r0 = wm * 16 + g;
        float inv0 = 1.f / S.l_s[r0];
        float inv1 = 1.f / S.l_s[r0 + 8];
        size_t base0 = (size_t)(b * LQ + q0 + r0) * (NH * DK) + h * DK;
        size_t base1 = (size_t)(b * LQ + q0 + r0 + 8) * (NH * DK) + h * DK;
#pragma unroll
        for (int nf = 0; nf < 4; ++nf) {
            int c = wn * 32 + nf * 8 + 2 * tg;
            *(float2*)(out + base0 + c) = make_float2(o[nf][0] * inv0, o[nf][1] * inv0);
            *(float2*)(out + base1 + c) = make_float2(o[nf][2] * inv1, o[nf][3] * inv1);
        }
    }
}

// ---------------------------------------------------------------------------
extern "C" void kernel_launch(void* const* d_in, const int* in_sizes, int n_in,
                              void* d_out, int out_size)
{
    const float* Q    = (const float*)d_in[0];
    const float* K    = (const float*)d_in[1];
    const float* V    = (const float*)d_in[2];
    const int*   mask = (const int*)d_in[3];
    const float* Wq   = (const float*)d_in[4];
    const float* bq   = (const float*)d_in[5];
    const float* Wk   = (const float*)d_in[6];
    const float* Wv   = (const float*)d_in[7];
    const float* bv   = (const float*)d_in[8];
    float* out = (float*)d_out;

    float *qp, *kp, *vp;
    cudaGetSymbolAddress((void**)&qp, g_q);
    cudaGetSymbolAddress((void**)&kp, g_k);
    cudaGetSymbolAddress((void**)&vp, g_v);

    cudaFuncSetAttribute(attn_mma, cudaFuncAttributeMaxDynamicSharedMemorySize,
                         (int)sizeof(AttnSmem));

    dim3 gproj(DM / PBN, (BB * LQ) / PBM);  // (16, 64)
    proj_mma<<<gproj, 256>>>(Q, Wq, bq,      qp, BB * LQ, NH * DK, DM);
    proj_mma<<<gproj, 256>>>(K, Wk, nullptr, kp, BB * LK, NH * DK, DM);
    proj_mma<<<gproj, 256>>>(V, Wv, bv,      vp, BB * LK, NH * DK, DM);

    dim3 gattn(LQ / 64, NH, BB);  // (32, 16, 4)
    attn_mma<<<gattn, 256, sizeof(AttnSmem)>>>(qp, kp, vp, mask, out);
}

// round 5
// speedup vs baseline: 3.3988x; 3.3988x over previous
#include <cuda_runtime.h>
#include <cuda_fp16.h>
#include <math.h>
#include <stdint.h>

#define BB 4
#define LQ 2048
#define LK 2048
#define DM 1024
#define NH 16
#define DK 64
#define NEGV -1000000000.0f

__device__ float g_q[BB * LQ * NH * DK];
__device__ float g_k[BB * LK * NH * DK];
__device__ float g_v[BB * LK * NH * DK];

__device__ __forceinline__ uint32_t smem_u32(const void* p) {
    uint32_t a;
    asm("{ .reg .u64 t; cvta.to.shared.u64 t, %1; cvt.u32.u64 %0, t; }"
        : "=r"(a) : "l"(p));
    return a;
}
__device__ __forceinline__ void ldm4(unsigned r[4], uint32_t a) {
    asm volatile("ldmatrix.sync.aligned.m8n8.x4.shared.b16 {%0,%1,%2,%3}, [%4];"
        : "=r"(r[0]), "=r"(r[1]), "=r"(r[2]), "=r"(r[3]) : "r"(a));
}
__device__ __forceinline__ void mma16(float c[4], const unsigned a[4],
                                      unsigned b0, unsigned b1) {
    asm volatile(
        "mma.sync.aligned.m16n8k16.row.col.f32.f16.f16.f32 "
        "{%0,%1,%2,%3},{%4,%5,%6,%7},{%8,%9},{%0,%1,%2,%3};"
        : "+f"(c[0]), "+f"(c[1]), "+f"(c[2]), "+f"(c[3])
        : "r"(a[0]), "r"(a[1]), "r"(a[2]), "r"(a[3]), "r"(b0), "r"(b1));
}
// Split fp32 pair into packed fp16 hi + fp16 lo.
__device__ __forceinline__ void split2x(float a, float b, uint32_t& hi, uint32_t& lo) {
    __half2 h = __floats2half2_rn(a, b);
    float2 hf = __half22float2(h);
    __half2 l = __floats2half2_rn(a - hf.x, b - hf.y);
    hi = *(uint32_t*)&h;
    lo = *(uint32_t*)&l;
}

// ---------------------------------------------------------------------------
// Projection: C[m][n] = sum_k A[m][k]*W[n][k] (+bias). BM=128 BN=64 BK=32.
// 8 warps: wm=warp&3 (32 rows), wn=warp>>2 (32 cols). fp16 3-term.
// ---------------------------------------------------------------------------
__global__ __launch_bounds__(256, 2) void proj_hmma(
    const float* __restrict__ A, const float* __restrict__ W,
    const float* __restrict__ bias, float* __restrict__ C)
{
    __shared__ __half Ah[128][40], Al[128][40];
    __shared__ __half Wh[64][40],  Wl[64][40];

    const int tid = threadIdx.x, warp = tid >> 5, lane = tid & 31;
    const int g = lane >> 2, tg = lane & 3;
    const int wm = warp & 3, wn = warp >> 2;
    const int bm = blockIdx.y * 128, bn = blockIdx.x * 64;

    const uint32_t ah_b = smem_u32(Ah), al_b = smem_u32(Al);
    const uint32_t wh_b = smem_u32(Wh), wl_b = smem_u32(Wl);
    const int lrow = lane & 15, lcol8 = (lane >> 4) << 3;

    float acc[2][4][4];
#pragma unroll
    for (int i = 0; i < 2; ++i)
#pragma unroll
        for (int j = 0; j < 4; ++j)
#pragma unroll
            for (int t = 0; t < 4; ++t) acc[i][j][t] = 0.f;

    for (int k0 = 0; k0 < DM; k0 += 32) {
        __syncthreads();
#pragma unroll
        for (int i = 0; i < 4; ++i) {            // A: 128x32
            int f4 = tid + i * 256;
            int r = f4 >> 3, c4 = (f4 & 7) * 4;
            float4 v = *(const float4*)(A + (size_t)(bm + r) * DM + k0 + c4);
            uint32_t h0, l0, h1, l1;
            split2x(v.x, v.y, h0, l0);
            split2x(v.z, v.w, h1, l1);
            *(uint32_t*)&Ah[r][c4] = h0; *(uint32_t*)&Ah[r][c4 + 2] = h1;
            *(uint32_t*)&Al[r][c4] = l0; *(uint32_t*)&Al[r][c4 + 2] = l1;
        }
#pragma unroll
        for (int i = 0; i < 2; ++i) {            // W: 64x32
            int f4 = tid + i * 256;
            int r = f4 >> 3, c4 = (f4 & 7) * 4;
            float4 v = *(const float4*)(W + (size_t)(bn + r) * DM + k0 + c4);
            uint32_t h0, l0, h1, l1;
            split2x(v.x, v.y, h0, l0);
            split2x(v.z, v.w, h1, l1);
            *(uint32_t*)&Wh[r][c4] = h0; *(uint32_t*)&Wh[r][c4 + 2] = h1;
            *(uint32_t*)&Wl[r][c4] = l0; *(uint32_t*)&Wl[r][c4 + 2] = l1;
        }
        __syncthreads();

#pragma unroll
        for (int kk = 0; kk < 32; kk += 16) {
            unsigned a_h[2][4], a_l[2][4], b_h[2][4], b_l[2][4];
#pragma unroll
            for (int mf = 0; mf < 2; ++mf) {
                uint32_t off = (uint32_t)((wm * 32 + mf * 16 + lrow) * 40 + kk + lcol8) * 2;
                ldm4(a_h[mf], ah_b + off);
                ldm4(a_l[mf], al_b + off);
            }
#pragma unroll
            for (int nh = 0; nh < 2; ++nh) {
                uint32_t off = (uint32_t)((wn * 32 + nh * 16 + lrow) * 40 + kk + lcol8) * 2;
                ldm4(b_h[nh], wh_b + off);
                ldm4(b_l[nh], wl_b + off);
            }
#pragma unroll
            for (int mf = 0; mf < 2; ++mf)
#pragma unroll
                for (int nh = 0; nh < 2; ++nh)
#pragma unroll
                    for (int j = 0; j < 2; ++j) {
                        int nf = nh * 2 + j;
                        mma16(acc[mf][nf], a_h[mf], b_h[nh][j], b_h[nh][2 + j]);
                        mma16(acc[mf][nf], a_l[mf], b_h[nh][j], b_h[nh][2 + j]);
                        mma16(acc[mf][nf], a_h[mf], b_l[nh][j], b_l[nh][2 + j]);
                    }
        }
    }

#pragma unroll
    for (int mf = 0; mf < 2; ++mf)
#pragma unroll
        for (int nf = 0; nf < 4; ++nf) {
            int r = bm + wm * 32 + mf * 16 + g;
            int c = bn + wn * 32 + (nf >> 1) * 16 + (nf & 1) * 8 + 2 * tg;
            float b0 = 0.f, b1 = 0.f;
            if (bias) { float2 bb = *(const float2*)(bias + c); b0 = bb.x; b1 = bb.y; }
            *(float2*)(C + (size_t)r * (NH * DK) + c) =
                make_float2(acc[mf][nf][0] + b0, acc[mf][nf][1] + b1);
            *(float2*)(C + (size_t)(r + 8) * (NH * DK) + c) =
                make_float2(acc[mf][nf][2] + b0, acc[mf][nf][3] + b1);
        }
}

// ---------------------------------------------------------------------------
// Flash attention: CTA = 128 queries x (b,h). KV tiles of 32.
// 8 warps, each owns 16 q-rows full width. fp16 hi/lo 3-term MMA + ldmatrix.
// ---------------------------------------------------------------------------
struct ASmem {
    __half Qh[128][72], Ql[128][72];
    __half Kh[32][72],  Kl[32][72];
    __half Vth[64][40], Vtl[64][40];   // V transposed: [d][kv]
    __half Ph[128][40], Pl[128][40];
    float  S[128][37];
    float  alpha[128];
    float  linv[128];
    int    msk[32];
};

__global__ __launch_bounds__(256, 2) void attn_hmma(
    const float* __restrict__ q, const float* __restrict__ k,
    const float* __restrict__ v, const int* __restrict__ mask,
    float* __restrict__ out)
{
    extern __shared__ char smraw[];
    ASmem& SM = *reinterpret_cast<ASmem*>(smraw);

    const int tid = threadIdx.x, warp = tid >> 5, lane = tid & 31;
    const int g = lane >> 2, tg = lane & 3;
    const int b = blockIdx.z, h = blockIdx.y;
    const int q0 = blockIdx.x * 128;

    const uint32_t qh_b = smem_u32(SM.Qh), ql_b = smem_u32(SM.Ql);
    const uint32_t kh_b = smem_u32(SM.Kh), kl_b = smem_u32(SM.Kl);
    const uint32_t vh_b = smem_u32(SM.Vth), vl_b = smem_u32(SM.Vtl);
    const uint32_t ph_b = smem_u32(SM.Ph), pl_b = smem_u32(SM.Pl);
    const int lrow = lane & 15, lcol8 = (lane >> 4) << 3;

    // Stage Q (128x64)
#pragma unroll
    for (int i = 0; i < 8; ++i) {
        int f4 = tid + i * 256;
        int r = f4 >> 4, c4 = (f4 & 15) * 4;
        float4 val = *(const float4*)(q + (size_t)(b * LQ + q0 + r) * (NH * DK) + h * DK + c4);
        uint32_t h0, l0, h1, l1;
        split2x(val.x, val.y, h0, l0);
        split2x(val.z, val.w, h1, l1);
        *(uint32_t*)&SM.Qh[r][c4] = h0; *(uint32_t*)&SM.Qh[r][c4 + 2] = h1;
        *(uint32_t*)&SM.Ql[r][c4] = l0; *(uint32_t*)&SM.Ql[r][c4 + 2] = l1;
    }

    float o[8][4];
#pragma unroll
    for (int i = 0; i < 8; ++i)
#pragma unroll
        for (int j = 0; j < 4; ++j) o[i][j] = 0.f;
    float mrun = -INFINITY, lrun = 0.f;

    for (int kt = 0; kt < LK; kt += 32) {
        __syncthreads();  // prior tile fully consumed

        // Stage K (32x64) + V transposed (64x32)
#pragma unroll
        for (int i = 0; i < 2; ++i) {
            int f4 = tid + i * 256;
            int r = f4 >> 4, c4 = (f4 & 15) * 4;
            size_t gi = (size_t)(b * LK + kt + r) * (NH * DK) + h * DK + c4;
            float4 kv4 = *(const float4*)(k + gi);
            uint32_t h0, l0, h1, l1;
            split2x(kv4.x, kv4.y, h0, l0);
            split2x(kv4.z, kv4.w, h1, l1);
            *(uint32_t*)&SM.Kh[r][c4] = h0; *(uint32_t*)&SM.Kh[r][c4 + 2] = h1;
            *(uint32_t*)&SM.Kl[r][c4] = l0; *(uint32_t*)&SM.Kl[r][c4 + 2] = l1;

            float4 vv4 = *(const float4*)(v + gi);
#pragma unroll
            for (int e = 0; e < 4; ++e) {
                float x = (e == 0) ? vv4.x : (e == 1) ? vv4.y : (e == 2) ? vv4.z : vv4.w;
                __half hh = __float2half_rn(x);
                __half ll = __float2half_rn(x - __half2float(hh));
                SM.Vth[c4 + e][r] = hh;
                SM.Vtl[c4 + e][r] = ll;
            }
        }
        if (tid < 32) SM.msk[tid] = mask[b * LK + kt + tid];
        __syncthreads();

        // ---- S = Q K^T (warp rows warp*16, 32 cols), 3-term ----
        float sa[4][4];
#pragma unroll
        for (int nf = 0; nf < 4; ++nf)
#pragma unroll
            for (int t = 0; t < 4; ++t) sa[nf][t] = 0.f;

#pragma unroll
        for (int kk = 0; kk < 64; kk += 16) {
            unsigned qa_h[4], qa_l[4];
            uint32_t qoff = (uint32_t)((warp * 16 + lrow) * 72 + kk + lcol8) * 2;
            ldm4(qa_h, qh_b + qoff);
            ldm4(qa_l, ql_b + qoff);
#pragma unroll
            for (int nh = 0; nh < 2; ++nh) {
                unsigned kb_h[4], kb_l[4];
                uint32_t koff = (uint32_t)((nh * 16 + lrow) * 72 + kk + lcol8) * 2;
                ldm4(kb_h, kh_b + koff);
                ldm4(kb_l, kl_b + koff);
#pragma unroll
                for (int j = 0; j < 2; ++j) {
                    int nf = nh * 2 + j;
                    mma16(sa[nf], qa_h, kb_h[j], kb_h[2 + j]);
                    mma16(sa[nf], qa_l, kb_h[j], kb_h[2 + j]);
                    mma16(sa[nf], qa_h, kb_l[j], kb_l[2 + j]);
                }
            }
        }
        {
            int r0 = warp * 16 + g;
#pragma unroll
            for (int nf = 0; nf < 4; ++nf) {
                int c = (nf >> 1) * 16 + (nf & 1) * 8 + 2 * tg;
                SM.S[r0][c]         = sa[nf][0] * 0.125f;
                SM.S[r0][c + 1]     = sa[nf][1] * 0.125f;
                SM.S[r0 + 8][c]     = sa[nf][2] * 0.125f;
                SM.S[r0 + 8][c + 1] = sa[nf][3] * 0.125f;
            }
        }
        __syncthreads();

        // ---- Online softmax: thread = q-row ----
        if (tid < 128) {
            const int r = tid;
            float sv[32];
            float mt = -INFINITY;
#pragma unroll
            for (int j = 0; j < 32; ++j) {
                float s = SM.msk[j] ? SM.S[r][j] : NEGV;
                sv[j] = s;
                mt = fmaxf(mt, s);
            }
            float mn = fmaxf(mrun, mt);
            float al = __expf(mrun - mn);
            float ls = 0.f;
#pragma unroll
            for (int j = 0; j < 32; j += 2) {
                float p0 = __expf(sv[j] - mn);
                float p1 = __expf(sv[j + 1] - mn);
                ls += p0 + p1;
                uint32_t hi, lo;
                split2x(p0, p1, hi, lo);
                *(uint32_t*)&SM.Ph[r][j] = hi;
                *(uint32_t*)&SM.Pl[r][j] = lo;
            }
            lrun = lrun * al + ls;
            mrun = mn;
            SM.alpha[r] = al;
        }
        __syncthreads();

        // ---- Rescale O, then O += P V ----
        {
            int r0 = warp * 16 + g;
            float a0 = SM.alpha[r0], a1 = SM.alpha[r0 + 8];
#pragma unroll
            for (int nf = 0; nf < 8; ++nf) {
                o[nf][0] *= a0; o[nf][1] *= a0;
                o[nf][2] *= a1; o[nf][3] *= a1;
            }
        }
#pragma unroll
        for (int kk = 0; kk < 32; kk += 16) {
            unsigned pa_h[4], pa_l[4];
            uint32_t poff = (uint32_t)((warp * 16 + lrow) * 40 + kk + lcol8) * 2;
            ldm4(pa_h, ph_b + poff);
            ldm4(pa_l, pl_b + poff);
#pragma unroll
            for (int dh = 0; dh < 4; ++dh) {
                unsigned vb_h[4], vb_l[4];
                uint32_t voff = (uint32_t)((dh * 16 + lrow) * 40 + kk + lcol8) * 2;
                ldm4(vb_h, vh_b + voff);
                ldm4(vb_l, vl_b + voff);
#pragma unroll
                for (int j = 0; j < 2; ++j) {
                    int nf = dh * 2 + j;
                    mma16(o[nf], pa_h, vb_h[j], vb_h[2 + j]);
                    mma16(o[nf], pa_l, vb_h[j], vb_h[2 + j]);
                    mma16(o[nf], pa_h, vb_l[j], vb_l[2 + j]);
                }
            }
        }
    }

    if (tid < 128) SM.linv[tid] = 1.f / lrun;
    __syncthreads();
    {
        int r0 = warp * 16 + g;
        float i0 = SM.linv[r0], i1 = SM.linv[r0 + 8];
        float* o0 = out + (size_t)(b * LQ + q0 + r0) * (NH * DK) + h * DK;
        float* o1 = out + (size_t)(b * LQ + q0 + r0 + 8) * (NH * DK) + h * DK;
#pragma unroll
        for (int nf = 0; nf < 8; ++nf) {
            int c = (nf >> 1) * 16 + (nf & 1) * 8 + 2 * tg;
            *(float2*)(o0 + c) = make_float2(o[nf][0] * i0, o[nf][1] * i0);
            *(float2*)(o1 + c) = make_float2(o[nf][2] * i1, o[nf][3] * i1);
        }
    }
}

// ---------------------------------------------------------------------------
extern "C" void kernel_launch(void* const* d_in, const int* in_sizes, int n_in,
                              void* d_out, int out_size)
{
    const float* Q    = (const float*)d_in[0];
    const float* K    = (const float*)d_in[1];
    const float* V    = (const float*)d_in[2];
    const int*   mask = (const int*)d_in[3];
    const float* Wq   = (const float*)d_in[4];
    const float* bq   = (const float*)d_in[5];
    const float* Wk   = (const float*)d_in[6];
    const float* Wv   = (const float*)d_in[7];
    const float* bv   = (const float*)d_in[8];
    float* out = (float*)d_out;

    float *qp, *kp, *vp;
    cudaGetSymbolAddress((void**)&qp, g_q);
    cudaGetSymbolAddress((void**)&kp, g_k);
    cudaGetSymbolAddress((void**)&vp, g_v);

    cudaFuncSetAttribute(attn_hmma, cudaFuncAttributeMaxDynamicSharedMemorySize,
                         (int)sizeof(ASmem));

    dim3 gproj((NH * DK) / 64, (BB * LQ) / 128);  // (16, 64)
    proj_hmma<<<gproj, 256>>>(Q, Wq, bq,      qp);
    proj_hmma<<<gproj, 256>>>(K, Wk, nullptr, kp);
    proj_hmma<<<gproj, 256>>>(V, Wv, bv,      vp);

    dim3 gattn(LQ / 128, NH, BB);  // (16, 16, 4)
    attn_hmma<<<gattn, 256, sizeof(ASmem)>>>(qp, kp, vp, mask, out);
}

// round 6
// speedup vs baseline: 4.0849x; 1.2019x over previous
#include <cuda_runtime.h>
#include <cuda_fp16.h>
#include <math.h>
#include <stdint.h>

#define BB 4
#define LQ 2048
#define LK 2048
#define DM 1024
#define NH 16
#define DK 64
#define NEGV -1000000000.0f

__device__ float g_q[BB * LQ * NH * DK];
__device__ float g_k[BB * LK * NH * DK];
__device__ float g_v[BB * LK * NH * DK];

__device__ __forceinline__ uint32_t smem_u32(const void* p) {
    uint32_t a;
    asm("{ .reg .u64 t; cvta.to.shared.u64 t, %1; cvt.u32.u64 %0, t; }"
        : "=r"(a) : "l"(p));
    return a;
}
__device__ __forceinline__ void ldm4(unsigned r[4], uint32_t a) {
    asm volatile("ldmatrix.sync.aligned.m8n8.x4.shared.b16 {%0,%1,%2,%3}, [%4];"
        : "=r"(r[0]), "=r"(r[1]), "=r"(r[2]), "=r"(r[3]) : "r"(a));
}
__device__ __forceinline__ void ldm4t(unsigned r[4], uint32_t a) {
    asm volatile("ldmatrix.sync.aligned.m8n8.x4.trans.shared.b16 {%0,%1,%2,%3}, [%4];"
        : "=r"(r[0]), "=r"(r[1]), "=r"(r[2]), "=r"(r[3]) : "r"(a));
}
__device__ __forceinline__ void mma16(float c[4], const unsigned a[4],
                                      unsigned b0, unsigned b1) {
    asm volatile(
        "mma.sync.aligned.m16n8k16.row.col.f32.f16.f16.f32 "
        "{%0,%1,%2,%3},{%4,%5,%6,%7},{%8,%9},{%0,%1,%2,%3};"
        : "+f"(c[0]), "+f"(c[1]), "+f"(c[2]), "+f"(c[3])
        : "r"(a[0]), "r"(a[1]), "r"(a[2]), "r"(a[3]), "r"(b0), "r"(b1));
}
// Split fp32 pair into packed fp16 hi + fp16 lo.
__device__ __forceinline__ void split2x(float a, float b, uint32_t& hi, uint32_t& lo) {
    __half2 h = __floats2half2_rn(a, b);
    float2 hf = __half22float2(h);
    __half2 l = __floats2half2_rn(a - hf.x, b - hf.y);
    hi = *(uint32_t*)&h;
    lo = *(uint32_t*)&l;
}

// ---------------------------------------------------------------------------
// Projection: C[m][n] = sum_k A[m][k]*W[n][k] (+bias). BM=128 BN=64 BK=32.
// (unchanged from R5 — fp16 3-term + ldmatrix)
// ---------------------------------------------------------------------------
__global__ __launch_bounds__(256, 2) void proj_hmma(
    const float* __restrict__ A, const float* __restrict__ W,
    const float* __restrict__ bias, float* __restrict__ C)
{
    __shared__ __half Ah[128][40], Al[128][40];
    __shared__ __half Wh[64][40],  Wl[64][40];

    const int tid = threadIdx.x, warp = tid >> 5, lane = tid & 31;
    const int g = lane >> 2, tg = lane & 3;
    const int wm = warp & 3, wn = warp >> 2;
    const int bm = blockIdx.y * 128, bn = blockIdx.x * 64;

    const uint32_t ah_b = smem_u32(Ah), al_b = smem_u32(Al);
    const uint32_t wh_b = smem_u32(Wh), wl_b = smem_u32(Wl);
    const int lrow = lane & 15, lcol8 = (lane >> 4) << 3;

    float acc[2][4][4];
#pragma unroll
    for (int i = 0; i < 2; ++i)
#pragma unroll
        for (int j = 0; j < 4; ++j)
#pragma unroll
            for (int t = 0; t < 4; ++t) acc[i][j][t] = 0.f;

    for (int k0 = 0; k0 < DM; k0 += 32) {
        __syncthreads();
#pragma unroll
        for (int i = 0; i < 4; ++i) {            // A: 128x32
            int f4 = tid + i * 256;
            int r = f4 >> 3, c4 = (f4 & 7) * 4;
            float4 v = *(const float4*)(A + (size_t)(bm + r) * DM + k0 + c4);
            uint32_t h0, l0, h1, l1;
            split2x(v.x, v.y, h0, l0);
            split2x(v.z, v.w, h1, l1);
            *(uint32_t*)&Ah[r][c4] = h0; *(uint32_t*)&Ah[r][c4 + 2] = h1;
            *(uint32_t*)&Al[r][c4] = l0; *(uint32_t*)&Al[r][c4 + 2] = l1;
        }
#pragma unroll
        for (int i = 0; i < 2; ++i) {            // W: 64x32
            int f4 = tid + i * 256;
            int r = f4 >> 3, c4 = (f4 & 7) * 4;
            float4 v = *(const float4*)(W + (size_t)(bn + r) * DM + k0 + c4);
            uint32_t h0, l0, h1, l1;
            split2x(v.x, v.y, h0, l0);
            split2x(v.z, v.w, h1, l1);
            *(uint32_t*)&Wh[r][c4] = h0; *(uint32_t*)&Wh[r][c4 + 2] = h1;
            *(uint32_t*)&Wl[r][c4] = l0; *(uint32_t*)&Wl[r][c4 + 2] = l1;
        }
        __syncthreads();

#pragma unroll
        for (int kk = 0; kk < 32; kk += 16) {
            unsigned a_h[2][4], a_l[2][4], b_h[2][4], b_l[2][4];
#pragma unroll
            for (int mf = 0; mf < 2; ++mf) {
                uint32_t off = (uint32_t)((wm * 32 + mf * 16 + lrow) * 40 + kk + lcol8) * 2;
                ldm4(a_h[mf], ah_b + off);
                ldm4(a_l[mf], al_b + off);
            }
#pragma unroll
            for (int nh = 0; nh < 2; ++nh) {
                uint32_t off = (uint32_t)((wn * 32 + nh * 16 + lrow) * 40 + kk + lcol8) * 2;
                ldm4(b_h[nh], wh_b + off);
                ldm4(b_l[nh], wl_b + off);
            }
#pragma unroll
            for (int mf = 0; mf < 2; ++mf)
#pragma unroll
                for (int nh = 0; nh < 2; ++nh)
#pragma unroll
                    for (int j = 0; j < 2; ++j) {
                        int nf = nh * 2 + j;
                        mma16(acc[mf][nf], a_h[mf], b_h[nh][j], b_h[nh][2 + j]);
                        mma16(acc[mf][nf], a_l[mf], b_h[nh][j], b_h[nh][2 + j]);
                        mma16(acc[mf][nf], a_h[mf], b_l[nh][j], b_l[nh][2 + j]);
                    }
        }
    }

#pragma unroll
    for (int mf = 0; mf < 2; ++mf)
#pragma unroll
        for (int nf = 0; nf < 4; ++nf) {
            int r = bm + wm * 32 + mf * 16 + g;
            int c = bn + wn * 32 + (nf >> 1) * 16 + (nf & 1) * 8 + 2 * tg;
            float b0 = 0.f, b1 = 0.f;
            if (bias) { float2 bb = *(const float2*)(bias + c); b0 = bb.x; b1 = bb.y; }
            *(float2*)(C + (size_t)r * (NH * DK) + c) =
                make_float2(acc[mf][nf][0] + b0, acc[mf][nf][1] + b1);
            *(float2*)(C + (size_t)(r + 8) * (NH * DK) + c) =
                make_float2(acc[mf][nf][2] + b0, acc[mf][nf][3] + b1);
        }
}

// ---------------------------------------------------------------------------
// Flash attention, fully register-resident softmax/P path.
// CTA = 128 queries x (b,h); 8 warps x 16 q-rows; KV tiles of 32.
// Q fragments in registers (loaded once from gmem). K via ldmatrix,
// V row-major via ldmatrix.trans. S/P never touch smem.
// ---------------------------------------------------------------------------
__global__ __launch_bounds__(256, 2) void attn_reg(
    const float* __restrict__ q, const float* __restrict__ k,
    const float* __restrict__ v, const int* __restrict__ mask,
    float* __restrict__ out)
{
    __shared__ __half Kh[32][72], Kl[32][72], Vh[32][72], Vl[32][72];
    __shared__ uint32_t mbw;

    const int tid = threadIdx.x, warp = tid >> 5, lane = tid & 31;
    const int g = lane >> 2, tg = lane & 3;
    const int b = blockIdx.z, h = blockIdx.y;
    const int q0 = blockIdx.x * 128;

    const uint32_t kh_b = smem_u32(Kh), kl_b = smem_u32(Kl);
    const uint32_t vh_b = smem_u32(Vh), vl_b = smem_u32(Vl);
    const int lrow = lane & 15, lcol8 = (lane >> 4) << 3;
    // ldmatrix.trans addressing for V (row-major [kv][d]) -> V^T fragments
    const int kvr  = (lane & 7) + ((lane >> 4) << 3);
    const int dcol = ((lane >> 3) & 1) * 8;

    // ---- Q fragments straight from gmem into registers ----
    unsigned qh[4][4], ql[4][4];
    {
        const float* qr0 = q + (size_t)(b * LQ + q0 + warp * 16 + g) * (NH * DK) + h * DK;
        const float* qr1 = qr0 + (size_t)8 * (NH * DK);
#pragma unroll
        for (int kk = 0; kk < 4; ++kk) {
            int c = kk * 16 + 2 * tg;
            float2 f0 = *(const float2*)(qr0 + c);
            float2 f1 = *(const float2*)(qr1 + c);
            float2 f2 = *(const float2*)(qr0 + c + 8);
            float2 f3 = *(const float2*)(qr1 + c + 8);
            split2x(f0.x, f0.y, qh[kk][0], ql[kk][0]);
            split2x(f1.x, f1.y, qh[kk][1], ql[kk][1]);
            split2x(f2.x, f2.y, qh[kk][2], ql[kk][2]);
            split2x(f3.x, f3.y, qh[kk][3], ql[kk][3]);
        }
    }

    float o[8][4];
#pragma unroll
    for (int i = 0; i < 8; ++i)
#pragma unroll
        for (int j = 0; j < 4; ++j) o[i][j] = 0.f;
    float mrA = -INFINITY, mrB = -INFINITY, lrA = 0.f, lrB = 0.f;

    for (int kt = 0; kt < LK; kt += 32) {
        __syncthreads();   // previous tile fully consumed

        // ---- Stage K and V (both row-major, vectorized) ----
#pragma unroll
        for (int i = 0; i < 2; ++i) {
            int f4 = tid + i * 256;
            int r = f4 >> 4, c4 = (f4 & 15) * 4;
            size_t gi = (size_t)(b * LK + kt + r) * (NH * DK) + h * DK + c4;
            float4 kv4 = *(const float4*)(k + gi);
            uint32_t h0, l0, h1, l1;
            split2x(kv4.x, kv4.y, h0, l0);
            split2x(kv4.z, kv4.w, h1, l1);
            *(uint32_t*)&Kh[r][c4] = h0; *(uint32_t*)&Kh[r][c4 + 2] = h1;
            *(uint32_t*)&Kl[r][c4] = l0; *(uint32_t*)&Kl[r][c4 + 2] = l1;
            float4 vv4 = *(const float4*)(v + gi);
            split2x(vv4.x, vv4.y, h0, l0);
            split2x(vv4.z, vv4.w, h1, l1);
            *(uint32_t*)&Vh[r][c4] = h0; *(uint32_t*)&Vh[r][c4 + 2] = h1;
            *(uint32_t*)&Vl[r][c4] = l0; *(uint32_t*)&Vl[r][c4 + 2] = l1;
        }
        if (warp == 0) {
            int mv = mask[b * LK + kt + lane];
            uint32_t bal = __ballot_sync(0xffffffffu, mv != 0);
            if (lane == 0) mbw = bal;
        }
        __syncthreads();
        const uint32_t mb = mbw;

        // ---- S = Q K^T (16 rows x 32 cols per warp), 3-term fp16 ----
        float sa[4][4];
#pragma unroll
        for (int nf = 0; nf < 4; ++nf)
#pragma unroll
            for (int t = 0; t < 4; ++t) sa[nf][t] = 0.f;

#pragma unroll
        for (int kk = 0; kk < 4; ++kk) {
#pragma unroll
            for (int nh = 0; nh < 2; ++nh) {
                unsigned kbh[4], kbl[4];
                uint32_t off = (uint32_t)((nh * 16 + lrow) * 72 + kk * 16 + lcol8) * 2;
                ldm4(kbh, kh_b + off);
                ldm4(kbl, kl_b + off);
#pragma unroll
                for (int j = 0; j < 2; ++j) {
                    int nf = nh * 2 + j;
                    mma16(sa[nf], qh[kk], kbh[j], kbh[2 + j]);
                    mma16(sa[nf], ql[kk], kbh[j], kbh[2 + j]);
                    mma16(sa[nf], qh[kk], kbl[j], kbl[2 + j]);
                }
            }
        }

        // ---- mask + scale + row max (rows: A = g, B = g+8) ----
        float mA = NEGV, mB = NEGV;
#pragma unroll
        for (int nf = 0; nf < 4; ++nf) {
            int c0 = nf * 8 + 2 * tg;
            bool k0 = (mb >> c0) & 1u;
            bool k1 = (mb >> (c0 + 1)) & 1u;
            sa[nf][0] = k0 ? sa[nf][0] * 0.125f : NEGV;
            sa[nf][1] = k1 ? sa[nf][1] * 0.125f : NEGV;
            sa[nf][2] = k0 ? sa[nf][2] * 0.125f : NEGV;
            sa[nf][3] = k1 ? sa[nf][3] * 0.125f : NEGV;
            mA = fmaxf(mA, fmaxf(sa[nf][0], sa[nf][1]));
            mB = fmaxf(mB, fmaxf(sa[nf][2], sa[nf][3]));
        }
        mA = fmaxf(mA, __shfl_xor_sync(0xffffffffu, mA, 1));
        mA = fmaxf(mA, __shfl_xor_sync(0xffffffffu, mA, 2));
        mB = fmaxf(mB, __shfl_xor_sync(0xffffffffu, mB, 1));
        mB = fmaxf(mB, __shfl_xor_sync(0xffffffffu, mB, 2));

        float mnA = fmaxf(mrA, mA), mnB = fmaxf(mrB, mB);
        float alA = __expf(mrA - mnA), alB = __expf(mrB - mnB);
        mrA = mnA; mrB = mnB;

        // ---- exp + build P fragments in registers ----
        unsigned pah[2][4], pal[2][4];
        float lsA = 0.f, lsB = 0.f;
#pragma unroll
        for (int jk = 0; jk < 2; ++jk) {
#pragma unroll
            for (int t = 0; t < 2; ++t) {
                int nf = jk * 2 + t;
                float p0 = __expf(sa[nf][0] - mnA);
                float p1 = __expf(sa[nf][1] - mnA);
                float p2 = __expf(sa[nf][2] - mnB);
                float p3 = __expf(sa[nf][3] - mnB);
                lsA += p0 + p1; lsB += p2 + p3;
                // A-frag order: a0=(rowA,k 2tg,2tg+1) a1=(rowB,..) a2=(rowA,+8) a3=(rowB,+8)
                split2x(p0, p1, pah[jk][2 * t],     pal[jk][2 * t]);
                split2x(p2, p3, pah[jk][2 * t + 1], pal[jk][2 * t + 1]);
            }
        }
        lsA += __shfl_xor_sync(0xffffffffu, lsA, 1);
        lsA += __shfl_xor_sync(0xffffffffu, lsA, 2);
        lsB += __shfl_xor_sync(0xffffffffu, lsB, 1);
        lsB += __shfl_xor_sync(0xffffffffu, lsB, 2);
        lrA = lrA * alA + lsA;
        lrB = lrB * alB + lsB;

        // ---- rescale O, then O += P V (V via trans-ldmatrix) ----
#pragma unroll
        for (int nf = 0; nf < 8; ++nf) {
            o[nf][0] *= alA; o[nf][1] *= alA;
            o[nf][2] *= alB; o[nf][3] *= alB;
        }
#pragma unroll
        for (int jk = 0; jk < 2; ++jk) {
#pragma unroll
            for (int dh = 0; dh < 4; ++dh) {
                unsigned vbh[4], vbl[4];
                uint32_t off = (uint32_t)((jk * 16 + kvr) * 72 + dh * 16 + dcol) * 2;
                ldm4t(vbh, vh_b + off);
                ldm4t(vbl, vl_b + off);
#pragma unroll
                for (int j = 0; j < 2; ++j) {
                    int nf = dh * 2 + j;
                    mma16(o[nf], pah[jk], vbh[j], vbh[2 + j]);
                    mma16(o[nf], pal[jk], vbh[j], vbh[2 + j]);
                    mma16(o[nf], pah[jk], vbl[j], vbl[2 + j]);
                }
            }
        }
    }

    // ---- normalize + store ----
    {
        float iA = 1.f / lrA, iB = 1.f / lrB;
        float* o0 = out + (size_t)(b * LQ + q0 + warp * 16 + g) * (NH * DK) + h * DK;
        float* o1 = o0 + (size_t)8 * (NH * DK);
#pragma unroll
        for (int nf = 0; nf < 8; ++nf) {
            int c = (nf >> 1) * 16 + (nf & 1) * 8 + 2 * tg;
            *(float2*)(o0 + c) = make_float2(o[nf][0] * iA, o[nf][1] * iA);
            *(float2*)(o1 + c) = make_float2(o[nf][2] * iB, o[nf][3] * iB);
        }
    }
}

// ---------------------------------------------------------------------------
extern "C" void kernel_launch(void* const* d_in, const int* in_sizes, int n_in,
                              void* d_out, int out_size)
{
    const float* Q    = (const float*)d_in[0];
    const float* K    = (const float*)d_in[1];
    const float* V    = (const float*)d_in[2];
    const int*   mask = (const int*)d_in[3];
    const float* Wq   = (const float*)d_in[4];
    const float* bq   = (const float*)d_in[5];
    const float* Wk   = (const float*)d_in[6];
    const float* Wv   = (const float*)d_in[7];
    const float* bv   = (const float*)d_in[8];
    float* out = (float*)d_out;

    float *qp, *kp, *vp;
    cudaGetSymbolAddress((void**)&qp, g_q);
    cudaGetSymbolAddress((void**)&kp, g_k);
    cudaGetSymbolAddress((void**)&vp, g_v);

    dim3 gproj((NH * DK) / 64, (BB * LQ) / 128);  // (16, 64)
    proj_hmma<<<gproj, 256>>>(Q, Wq, bq,      qp);
    proj_hmma<<<gproj, 256>>>(K, Wk, nullptr, kp);
    proj_hmma<<<gproj, 256>>>(V, Wv, bv,      vp);

    dim3 gattn(LQ / 128, NH, BB);  // (16, 16, 4)
    attn_reg<<<gattn, 256>>>(qp, kp, vp, mask, out);
}

// round 7
// speedup vs baseline: 4.4748x; 1.0954x over previous
#include <cuda_runtime.h>
#include <cuda_fp16.h>
#include <math.h>
#include <stdint.h>

#define BB 4
#define LQ 2048
#define LK 2048
#define DM 1024
#define NH 16
#define DK 64
#define NEGV -1000000000.0f

// Pre-split fp16 hi/lo projected tensors: [B*LEN, NH*DK]
__device__ __half g_qh[BB * LQ * NH * DK];
__device__ __half g_ql[BB * LQ * NH * DK];
__device__ __half g_kh[BB * LK * NH * DK];
__device__ __half g_kl[BB * LK * NH * DK];
__device__ __half g_vh[BB * LK * NH * DK];
__device__ __half g_vl[BB * LK * NH * DK];

__device__ __forceinline__ uint32_t smem_u32(const void* p) {
    uint32_t a;
    asm("{ .reg .u64 t; cvta.to.shared.u64 t, %1; cvt.u32.u64 %0, t; }"
        : "=r"(a) : "l"(p));
    return a;
}
__device__ __forceinline__ void ldm4(unsigned r[4], uint32_t a) {
    asm volatile("ldmatrix.sync.aligned.m8n8.x4.shared.b16 {%0,%1,%2,%3}, [%4];"
        : "=r"(r[0]), "=r"(r[1]), "=r"(r[2]), "=r"(r[3]) : "r"(a));
}
__device__ __forceinline__ void ldm4t(unsigned r[4], uint32_t a) {
    asm volatile("ldmatrix.sync.aligned.m8n8.x4.trans.shared.b16 {%0,%1,%2,%3}, [%4];"
        : "=r"(r[0]), "=r"(r[1]), "=r"(r[2]), "=r"(r[3]) : "r"(a));
}
__device__ __forceinline__ void mma16(float c[4], const unsigned a[4],
                                      unsigned b0, unsigned b1) {
    asm volatile(
        "mma.sync.aligned.m16n8k16.row.col.f32.f16.f16.f32 "
        "{%0,%1,%2,%3},{%4,%5,%6,%7},{%8,%9},{%0,%1,%2,%3};"
        : "+f"(c[0]), "+f"(c[1]), "+f"(c[2]), "+f"(c[3])
        : "r"(a[0]), "r"(a[1]), "r"(a[2]), "r"(a[3]), "r"(b0), "r"(b1));
}
__device__ __forceinline__ void split2x(float a, float b, uint32_t& hi, uint32_t& lo) {
    __half2 h = __floats2half2_rn(a, b);
    float2 hf = __half22float2(h);
    __half2 l = __floats2half2_rn(a - hf.x, b - hf.y);
    hi = *(uint32_t*)&h;
    lo = *(uint32_t*)&l;
}
#define CP16(dst, src) \
    asm volatile("cp.async.cg.shared.global [%0], [%1], 16;" \
                 :: "r"(dst), "l"(src) : "memory")
#define CPCOMMIT() asm volatile("cp.async.commit_group;" ::: "memory")
#define CPWAIT0()  asm volatile("cp.async.wait_group 0;" ::: "memory")

// ---------------------------------------------------------------------------
// Fused projections (z = 0:Q scaled by 1/8, 1:K, 2:V). BM=128 BN=64 BK=32.
// fp16 3-term HMMA; epilogue stores pre-split half hi/lo.
// ---------------------------------------------------------------------------
__global__ __launch_bounds__(256, 2) void proj_hmma(
    const float* __restrict__ Qin, const float* __restrict__ Kin,
    const float* __restrict__ Vin,
    const float* __restrict__ Wq, const float* __restrict__ bq,
    const float* __restrict__ Wk,
    const float* __restrict__ Wv, const float* __restrict__ bv)
{
    const float *A, *W, *bias;
    __half *Ch, *Cl;
    float scale;
    if (blockIdx.z == 0)      { A = Qin; W = Wq; bias = bq;      Ch = g_qh; Cl = g_ql; scale = 0.125f; }
    else if (blockIdx.z == 1) { A = Kin; W = Wk; bias = nullptr; Ch = g_kh; Cl = g_kl; scale = 1.f; }
    else                      { A = Vin; W = Wv; bias = bv;      Ch = g_vh; Cl = g_vl; scale = 1.f; }

    __shared__ __half Ah[128][40], Al[128][40];
    __shared__ __half Wh[64][40],  Wl[64][40];

    const int tid = threadIdx.x, warp = tid >> 5, lane = tid & 31;
    const int g = lane >> 2, tg = lane & 3;
    const int wm = warp & 3, wn = warp >> 2;
    const int bm = blockIdx.y * 128, bn = blockIdx.x * 64;

    const uint32_t ah_b = smem_u32(Ah), al_b = smem_u32(Al);
    const uint32_t wh_b = smem_u32(Wh), wl_b = smem_u32(Wl);
    const int lrow = lane & 15, lcol8 = (lane >> 4) << 3;

    float acc[2][4][4];
#pragma unroll
    for (int i = 0; i < 2; ++i)
#pragma unroll
        for (int j = 0; j < 4; ++j)
#pragma unroll
            for (int t = 0; t < 4; ++t) acc[i][j][t] = 0.f;

    for (int k0 = 0; k0 < DM; k0 += 32) {
        __syncthreads();
#pragma unroll
        for (int i = 0; i < 4; ++i) {            // A: 128x32
            int f4 = tid + i * 256;
            int r = f4 >> 3, c4 = (f4 & 7) * 4;
            float4 v = *(const float4*)(A + (size_t)(bm + r) * DM + k0 + c4);
            uint32_t h0, l0, h1, l1;
            split2x(v.x, v.y, h0, l0);
            split2x(v.z, v.w, h1, l1);
            *(uint32_t*)&Ah[r][c4] = h0; *(uint32_t*)&Ah[r][c4 + 2] = h1;
            *(uint32_t*)&Al[r][c4] = l0; *(uint32_t*)&Al[r][c4 + 2] = l1;
        }
#pragma unroll
        for (int i = 0; i < 2; ++i) {            // W: 64x32
            int f4 = tid + i * 256;
            int r = f4 >> 3, c4 = (f4 & 7) * 4;
            float4 v = *(const float4*)(W + (size_t)(bn + r) * DM + k0 + c4);
            uint32_t h0, l0, h1, l1;
            split2x(v.x, v.y, h0, l0);
            split2x(v.z, v.w, h1, l1);
            *(uint32_t*)&Wh[r][c4] = h0; *(uint32_t*)&Wh[r][c4 + 2] = h1;
            *(uint32_t*)&Wl[r][c4] = l0; *(uint32_t*)&Wl[r][c4 + 2] = l1;
        }
        __syncthreads();

#pragma unroll
        for (int kk = 0; kk < 32; kk += 16) {
            unsigned a_h[2][4], a_l[2][4], b_h[2][4], b_l[2][4];
#pragma unroll
            for (int mf = 0; mf < 2; ++mf) {
                uint32_t off = (uint32_t)((wm * 32 + mf * 16 + lrow) * 40 + kk + lcol8) * 2;
                ldm4(a_h[mf], ah_b + off);
                ldm4(a_l[mf], al_b + off);
            }
#pragma unroll
            for (int nh = 0; nh < 2; ++nh) {
                uint32_t off = (uint32_t)((wn * 32 + nh * 16 + lrow) * 40 + kk + lcol8) * 2;
                ldm4(b_h[nh], wh_b + off);
                ldm4(b_l[nh], wl_b + off);
            }
#pragma unroll
            for (int mf = 0; mf < 2; ++mf)
#pragma unroll
                for (int nh = 0; nh < 2; ++nh)
#pragma unroll
                    for (int j = 0; j < 2; ++j) {
                        int nf = nh * 2 + j;
                        mma16(acc[mf][nf], a_h[mf], b_h[nh][j], b_h[nh][2 + j]);
                        mma16(acc[mf][nf], a_l[mf], b_h[nh][j], b_h[nh][2 + j]);
                        mma16(acc[mf][nf], a_h[mf], b_l[nh][j], b_l[nh][2 + j]);
                    }
        }
    }

#pragma unroll
    for (int mf = 0; mf < 2; ++mf)
#pragma unroll
        for (int nf = 0; nf < 4; ++nf) {
            int r = bm + wm * 32 + mf * 16 + g;
            int c = bn + wn * 32 + (nf >> 1) * 16 + (nf & 1) * 8 + 2 * tg;
            float b0 = 0.f, b1 = 0.f;
            if (bias) { float2 bb = *(const float2*)(bias + c); b0 = bb.x; b1 = bb.y; }
            uint32_t hi, lo;
            split2x((acc[mf][nf][0] + b0) * scale, (acc[mf][nf][1] + b1) * scale, hi, lo);
            *(uint32_t*)(Ch + (size_t)r * (NH * DK) + c) = hi;
            *(uint32_t*)(Cl + (size_t)r * (NH * DK) + c) = lo;
            split2x((acc[mf][nf][2] + b0) * scale, (acc[mf][nf][3] + b1) * scale, hi, lo);
            *(uint32_t*)(Ch + (size_t)(r + 8) * (NH * DK) + c) = hi;
            *(uint32_t*)(Cl + (size_t)(r + 8) * (NH * DK) + c) = lo;
        }
}

// ---------------------------------------------------------------------------
// Flash attention: pre-split inputs, cp.async double-buffered K/V staging,
// register-resident softmax/P. CTA = 128 q x (b,h); 8 warps; KV tiles of 32.
// ---------------------------------------------------------------------------
__global__ __launch_bounds__(256, 2) void attn_reg(
    const int* __restrict__ mask, float* __restrict__ out)
{
    __shared__ __half Ksh[2][32][72], Ksl[2][32][72];
    __shared__ __half Vsh[2][32][72], Vsl[2][32][72];
    __shared__ uint32_t mbw[2];

    const int tid = threadIdx.x, warp = tid >> 5, lane = tid & 31;
    const int g = lane >> 2, tg = lane & 3;
    const int b = blockIdx.z, h = blockIdx.y;
    const int q0 = blockIdx.x * 128;

    const int lrow = lane & 15, lcol8 = (lane >> 4) << 3;
    const int kvr  = (lane & 7) + ((lane >> 4) << 3);   // trans-ldmatrix row
    const int dcol = ((lane >> 3) & 1) * 8;

    // copy geometry: thread -> (row, 8-half column chunk)
    const int cr = tid >> 3, cc = (tid & 7) * 8;

    // ---- Q fragments direct from pre-split gmem (already scaled by 1/8) ----
    unsigned qfh[4][4], qfl[4][4];
    {
        size_t r0 = (size_t)(b * LQ + q0 + warp * 16 + g) * (NH * DK) + h * DK;
        size_t r1 = r0 + (size_t)8 * (NH * DK);
#pragma unroll
        for (int kk = 0; kk < 4; ++kk) {
            int c = kk * 16 + 2 * tg;
            qfh[kk][0] = *(const uint32_t*)(g_qh + r0 + c);
            qfh[kk][1] = *(const uint32_t*)(g_qh + r1 + c);
            qfh[kk][2] = *(const uint32_t*)(g_qh + r0 + c + 8);
            qfh[kk][3] = *(const uint32_t*)(g_qh + r1 + c + 8);
            qfl[kk][0] = *(const uint32_t*)(g_ql + r0 + c);
            qfl[kk][1] = *(const uint32_t*)(g_ql + r1 + c);
            qfl[kk][2] = *(const uint32_t*)(g_ql + r0 + c + 8);
            qfl[kk][3] = *(const uint32_t*)(g_ql + r1 + c + 8);
        }
    }

    float o[8][4];
#pragma unroll
    for (int i = 0; i < 8; ++i)
#pragma unroll
        for (int j = 0; j < 4; ++j) o[i][j] = 0.f;
    float mrA = -INFINITY, mrB = -INFINITY, lrA = 0.f, lrB = 0.f;

    // ---- prime tile 0 ----
    {
        size_t goff = (size_t)(b * LK + cr) * (NH * DK) + h * DK + cc;
        CP16(smem_u32(&Ksh[0][cr][cc]), g_kh + goff);
        CP16(smem_u32(&Ksl[0][cr][cc]), g_kl + goff);
        CP16(smem_u32(&Vsh[0][cr][cc]), g_vh + goff);
        CP16(smem_u32(&Vsl[0][cr][cc]), g_vl + goff);
        CPCOMMIT();
        if (warp == 0) {
            uint32_t bal = __ballot_sync(0xffffffffu, mask[b * LK + lane] != 0);
            if (lane == 0) mbw[0] = bal;
        }
    }

    int buf = 0;
    for (int kt = 0; kt < LK; kt += 32) {
        CPWAIT0();
        __syncthreads();   // copies visible; previous compute on buf^1 done

        if (kt + 32 < LK) {
            size_t goff = (size_t)(b * LK + kt + 32 + cr) * (NH * DK) + h * DK + cc;
            int nb = buf ^ 1;
            CP16(smem_u32(&Ksh[nb][cr][cc]), g_kh + goff);
            CP16(smem_u32(&Ksl[nb][cr][cc]), g_kl + goff);
            CP16(smem_u32(&Vsh[nb][cr][cc]), g_vh + goff);
            CP16(smem_u32(&Vsl[nb][cr][cc]), g_vl + goff);
            CPCOMMIT();
            if (warp == 0) {
                uint32_t bal = __ballot_sync(0xffffffffu,
                                             mask[b * LK + kt + 32 + lane] != 0);
                if (lane == 0) mbw[nb] = bal;
            }
        }
        const uint32_t mb = mbw[buf];
        const uint32_t kh_b = smem_u32(&Ksh[buf][0][0]);
        const uint32_t kl_b = smem_u32(&Ksl[buf][0][0]);
        const uint32_t vh_b = smem_u32(&Vsh[buf][0][0]);
        const uint32_t vl_b = smem_u32(&Vsl[buf][0][0]);

        // ---- S = Q K^T (16 rows x 32 cols per warp), 3-term fp16 ----
        float sa[4][4];
#pragma unroll
        for (int nf = 0; nf < 4; ++nf)
#pragma unroll
            for (int t = 0; t < 4; ++t) sa[nf][t] = 0.f;

#pragma unroll
        for (int kk = 0; kk < 4; ++kk) {
#pragma unroll
            for (int nh = 0; nh < 2; ++nh) {
                unsigned kbh[4], kbl[4];
                uint32_t off = (uint32_t)((nh * 16 + lrow) * 72 + kk * 16 + lcol8) * 2;
                ldm4(kbh, kh_b + off);
                ldm4(kbl, kl_b + off);
#pragma unroll
                for (int j = 0; j < 2; ++j) {
                    int nf = nh * 2 + j;
                    mma16(sa[nf], qfh[kk], kbh[j], kbh[2 + j]);
                    mma16(sa[nf], qfl[kk], kbh[j], kbh[2 + j]);
                    mma16(sa[nf], qfh[kk], kbl[j], kbl[2 + j]);
                }
            }
        }

        // ---- mask + row max (scale pre-folded into Q) ----
        float mA = NEGV, mB = NEGV;
#pragma unroll
        for (int nf = 0; nf < 4; ++nf) {
            int c0 = nf * 8 + 2 * tg;
            bool k0 = (mb >> c0) & 1u;
            bool k1 = (mb >> (c0 + 1)) & 1u;
            sa[nf][0] = k0 ? sa[nf][0] : NEGV;
            sa[nf][1] = k1 ? sa[nf][1] : NEGV;
            sa[nf][2] = k0 ? sa[nf][2] : NEGV;
            sa[nf][3] = k1 ? sa[nf][3] : NEGV;
            mA = fmaxf(mA, fmaxf(sa[nf][0], sa[nf][1]));
            mB = fmaxf(mB, fmaxf(sa[nf][2], sa[nf][3]));
        }
        mA = fmaxf(mA, __shfl_xor_sync(0xffffffffu, mA, 1));
        mA = fmaxf(mA, __shfl_xor_sync(0xffffffffu, mA, 2));
        mB = fmaxf(mB, __shfl_xor_sync(0xffffffffu, mB, 1));
        mB = fmaxf(mB, __shfl_xor_sync(0xffffffffu, mB, 2));

        float mnA = fmaxf(mrA, mA), mnB = fmaxf(mrB, mB);
        float alA = __expf(mrA - mnA), alB = __expf(mrB - mnB);
        mrA = mnA; mrB = mnB;

        // ---- exp + build P fragments in registers ----
        unsigned pah[2][4], pal[2][4];
        float lsA = 0.f, lsB = 0.f;
#pragma unroll
        for (int jk = 0; jk < 2; ++jk) {
#pragma unroll
            for (int t = 0; t < 2; ++t) {
                int nf = jk * 2 + t;
                float p0 = __expf(sa[nf][0] - mnA);
                float p1 = __expf(sa[nf][1] - mnA);
                float p2 = __expf(sa[nf][2] - mnB);
                float p3 = __expf(sa[nf][3] - mnB);
                lsA += p0 + p1; lsB += p2 + p3;
                split2x(p0, p1, pah[jk][2 * t],     pal[jk][2 * t]);
                split2x(p2, p3, pah[jk][2 * t + 1], pal[jk][2 * t + 1]);
            }
        }
        lsA += __shfl_xor_sync(0xffffffffu, lsA, 1);
        lsA += __shfl_xor_sync(0xffffffffu, lsA, 2);
        lsB += __shfl_xor_sync(0xffffffffu, lsB, 1);
        lsB += __shfl_xor_sync(0xffffffffu, lsB, 2);
        lrA = lrA * alA + lsA;
        lrB = lrB * alB + lsB;

        // ---- rescale O, then O += P V ----
#pragma unroll
        for (int nf = 0; nf < 8; ++nf) {
            o[nf][0] *= alA; o[nf][1] *= alA;
            o[nf][2] *= alB; o[nf][3] *= alB;
        }
#pragma unroll
        for (int jk = 0; jk < 2; ++jk) {
#pragma unroll
            for (int dh = 0; dh < 4; ++dh) {
                unsigned vbh[4], vbl[4];
                uint32_t off = (uint32_t)((jk * 16 + kvr) * 72 + dh * 16 + dcol) * 2;
                ldm4t(vbh, vh_b + off);
                ldm4t(vbl, vl_b + off);
#pragma unroll
                for (int j = 0; j < 2; ++j) {
                    int nf = dh * 2 + j;
                    mma16(o[nf], pah[jk], vbh[j], vbh[2 + j]);
                    mma16(o[nf], pal[jk], vbh[j], vbh[2 + j]);
                    mma16(o[nf], pah[jk], vbl[j], vbl[2 + j]);
                }
            }
        }
        buf ^= 1;
    }

    // ---- normalize + store ----
    {
        float iA = 1.f / lrA, iB = 1.f / lrB;
        float* o0 = out + (size_t)(b * LQ + q0 + warp * 16 + g) * (NH * DK) + h * DK;
        float* o1 = o0 + (size_t)8 * (NH * DK);
#pragma unroll
        for (int nf = 0; nf < 8; ++nf) {
            int c = (nf >> 1) * 16 + (nf & 1) * 8 + 2 * tg;
            *(float2*)(o0 + c) = make_float2(o[nf][0] * iA, o[nf][1] * iA);
            *(float2*)(o1 + c) = make_float2(o[nf][2] * iB, o[nf][3] * iB);
        }
    }
}

// ---------------------------------------------------------------------------
extern "C" void kernel_launch(void* const* d_in, const int* in_sizes, int n_in,
                              void* d_out, int out_size)
{
    const float* Q    = (const float*)d_in[0];
    const float* K    = (const float*)d_in[1];
    const float* V    = (const float*)d_in[2];
    const int*   mask = (const int*)d_in[3];
    const float* Wq   = (const float*)d_in[4];
    const float* bq   = (const float*)d_in[5];
    const float* Wk   = (const float*)d_in[6];
    const float* Wv   = (const float*)d_in[7];
    const float* bv   = (const float*)d_in[8];
    float* out = (float*)d_out;

    dim3 gproj((NH * DK) / 64, (BB * LQ) / 128, 3);  // (16, 64, 3)
    proj_hmma<<<gproj, 256>>>(Q, K, V, Wq, bq, Wk, Wv, bv);

    dim3 gattn(LQ / 128, NH, BB);  // (16, 16, 4)
    attn_reg<<<gattn, 256>>>(mask, out);
}

// round 8
// speedup vs baseline: 4.7813x; 1.0685x over previous
#include <cuda_runtime.h>
#include <cuda_fp16.h>
#include <math.h>
#include <stdint.h>

#define BB 4
#define LQ 2048
#define LK 2048
#define DM 1024
#define NH 16
#define DK 64
#define NEGV -1000000000.0f

// Pre-split fp16 hi/lo projected tensors: [B*LEN, NH*DK]
__device__ __half g_qh[BB * LQ * NH * DK];
__device__ __half g_ql[BB * LQ * NH * DK];
__device__ __half g_kh[BB * LK * NH * DK];
__device__ __half g_kl[BB * LK * NH * DK];
__device__ __half g_vh[BB * LK * NH * DK];
__device__ __half g_vl[BB * LK * NH * DK];

__device__ __forceinline__ uint32_t smem_u32(const void* p) {
    uint32_t a;
    asm("{ .reg .u64 t; cvta.to.shared.u64 t, %1; cvt.u32.u64 %0, t; }"
        : "=r"(a) : "l"(p));
    return a;
}
__device__ __forceinline__ void ldm4(unsigned r[4], uint32_t a) {
    asm volatile("ldmatrix.sync.aligned.m8n8.x4.shared.b16 {%0,%1,%2,%3}, [%4];"
        : "=r"(r[0]), "=r"(r[1]), "=r"(r[2]), "=r"(r[3]) : "r"(a));
}
__device__ __forceinline__ void ldm4t(unsigned r[4], uint32_t a) {
    asm volatile("ldmatrix.sync.aligned.m8n8.x4.trans.shared.b16 {%0,%1,%2,%3}, [%4];"
        : "=r"(r[0]), "=r"(r[1]), "=r"(r[2]), "=r"(r[3]) : "r"(a));
}
__device__ __forceinline__ void mma16(float c[4], const unsigned a[4],
                                      unsigned b0, unsigned b1) {
    asm volatile(
        "mma.sync.aligned.m16n8k16.row.col.f32.f16.f16.f32 "
        "{%0,%1,%2,%3},{%4,%5,%6,%7},{%8,%9},{%0,%1,%2,%3};"
        : "+f"(c[0]), "+f"(c[1]), "+f"(c[2]), "+f"(c[3])
        : "r"(a[0]), "r"(a[1]), "r"(a[2]), "r"(a[3]), "r"(b0), "r"(b1));
}
__device__ __forceinline__ void split2x(float a, float b, uint32_t& hi, uint32_t& lo) {
    __half2 h = __floats2half2_rn(a, b);
    float2 hf = __half22float2(h);
    __half2 l = __floats2half2_rn(a - hf.x, b - hf.y);
    hi = *(uint32_t*)&h;
    lo = *(uint32_t*)&l;
}
__device__ __forceinline__ uint32_t pack_h2(float a, float b) {
    __half2 h = __floats2half2_rn(a, b);
    return *(uint32_t*)&h;
}
#define CP16(dst, src) \
    asm volatile("cp.async.cg.shared.global [%0], [%1], 16;" \
                 :: "r"(dst), "l"(src) : "memory")
#define CPCOMMIT() asm volatile("cp.async.commit_group;" ::: "memory")
#define CPWAIT0()  asm volatile("cp.async.wait_group 0;" ::: "memory")

// ---------------------------------------------------------------------------
// Fused projections (z = 0:Q scaled by 1/8, 1:K, 2:V). BM=128 BN=64 BK=32.
// fp16 3-term HMMA; epilogue stores pre-split half hi/lo.
// ---------------------------------------------------------------------------
__global__ __launch_bounds__(256, 2) void proj_hmma(
    const float* __restrict__ Qin, const float* __restrict__ Kin,
    const float* __restrict__ Vin,
    const float* __restrict__ Wq, const float* __restrict__ bq,
    const float* __restrict__ Wk,
    const float* __restrict__ Wv, const float* __restrict__ bv)
{
    const float *A, *W, *bias;
    __half *Ch, *Cl;
    float scale;
    if (blockIdx.z == 0)      { A = Qin; W = Wq; bias = bq;      Ch = g_qh; Cl = g_ql; scale = 0.125f; }
    else if (blockIdx.z == 1) { A = Kin; W = Wk; bias = nullptr; Ch = g_kh; Cl = g_kl; scale = 1.f; }
    else                      { A = Vin; W = Wv; bias = bv;      Ch = g_vh; Cl = g_vl; scale = 1.f; }

    __shared__ __half Ah[128][40], Al[128][40];
    __shared__ __half Wh[64][40],  Wl[64][40];

    const int tid = threadIdx.x, warp = tid >> 5, lane = tid & 31;
    const int g = lane >> 2, tg = lane & 3;
    const int wm = warp & 3, wn = warp >> 2;
    const int bm = blockIdx.y * 128, bn = blockIdx.x * 64;

    const uint32_t ah_b = smem_u32(Ah), al_b = smem_u32(Al);
    const uint32_t wh_b = smem_u32(Wh), wl_b = smem_u32(Wl);
    const int lrow = lane & 15, lcol8 = (lane >> 4) << 3;

    float acc[2][4][4];
#pragma unroll
    for (int i = 0; i < 2; ++i)
#pragma unroll
        for (int j = 0; j < 4; ++j)
#pragma unroll
            for (int t = 0; t < 4; ++t) acc[i][j][t] = 0.f;

    for (int k0 = 0; k0 < DM; k0 += 32) {
        __syncthreads();
#pragma unroll
        for (int i = 0; i < 4; ++i) {            // A: 128x32
            int f4 = tid + i * 256;
            int r = f4 >> 3, c4 = (f4 & 7) * 4;
            float4 v = *(const float4*)(A + (size_t)(bm + r) * DM + k0 + c4);
            uint32_t h0, l0, h1, l1;
            split2x(v.x, v.y, h0, l0);
            split2x(v.z, v.w, h1, l1);
            *(uint32_t*)&Ah[r][c4] = h0; *(uint32_t*)&Ah[r][c4 + 2] = h1;
            *(uint32_t*)&Al[r][c4] = l0; *(uint32_t*)&Al[r][c4 + 2] = l1;
        }
#pragma unroll
        for (int i = 0; i < 2; ++i) {            // W: 64x32
            int f4 = tid + i * 256;
            int r = f4 >> 3, c4 = (f4 & 7) * 4;
            float4 v = *(const float4*)(W + (size_t)(bn + r) * DM + k0 + c4);
            uint32_t h0, l0, h1, l1;
            split2x(v.x, v.y, h0, l0);
            split2x(v.z, v.w, h1, l1);
            *(uint32_t*)&Wh[r][c4] = h0; *(uint32_t*)&Wh[r][c4 + 2] = h1;
            *(uint32_t*)&Wl[r][c4] = l0; *(uint32_t*)&Wl[r][c4 + 2] = l1;
        }
        __syncthreads();

#pragma unroll
        for (int kk = 0; kk < 32; kk += 16) {
            unsigned a_h[2][4], a_l[2][4], b_h[2][4], b_l[2][4];
#pragma unroll
            for (int mf = 0; mf < 2; ++mf) {
                uint32_t off = (uint32_t)((wm * 32 + mf * 16 + lrow) * 40 + kk + lcol8) * 2;
                ldm4(a_h[mf], ah_b + off);
                ldm4(a_l[mf], al_b + off);
            }
#pragma unroll
            for (int nh = 0; nh < 2; ++nh) {
                uint32_t off = (uint32_t)((wn * 32 + nh * 16 + lrow) * 40 + kk + lcol8) * 2;
                ldm4(b_h[nh], wh_b + off);
                ldm4(b_l[nh], wl_b + off);
            }
#pragma unroll
            for (int mf = 0; mf < 2; ++mf)
#pragma unroll
                for (int nh = 0; nh < 2; ++nh)
#pragma unroll
                    for (int j = 0; j < 2; ++j) {
                        int nf = nh * 2 + j;
                        mma16(acc[mf][nf], a_h[mf], b_h[nh][j], b_h[nh][2 + j]);
                        mma16(acc[mf][nf], a_l[mf], b_h[nh][j], b_h[nh][2 + j]);
                        mma16(acc[mf][nf], a_h[mf], b_l[nh][j], b_l[nh][2 + j]);
                    }
        }
    }

#pragma unroll
    for (int mf = 0; mf < 2; ++mf)
#pragma unroll
        for (int nf = 0; nf < 4; ++nf) {
            int r = bm + wm * 32 + mf * 16 + g;
            int c = bn + wn * 32 + (nf >> 1) * 16 + (nf & 1) * 8 + 2 * tg;
            float b0 = 0.f, b1 = 0.f;
            if (bias) { float2 bb = *(const float2*)(bias + c); b0 = bb.x; b1 = bb.y; }
            uint32_t hi, lo;
            split2x((acc[mf][nf][0] + b0) * scale, (acc[mf][nf][1] + b1) * scale, hi, lo);
            *(uint32_t*)(Ch + (size_t)r * (NH * DK) + c) = hi;
            *(uint32_t*)(Cl + (size_t)r * (NH * DK) + c) = lo;
            split2x((acc[mf][nf][2] + b0) * scale, (acc[mf][nf][3] + b1) * scale, hi, lo);
            *(uint32_t*)(Ch + (size_t)(r + 8) * (NH * DK) + c) = hi;
            *(uint32_t*)(Cl + (size_t)(r + 8) * (NH * DK) + c) = lo;
        }
}

// ---------------------------------------------------------------------------
// Flash attention: pre-split inputs, cp.async double buffering (compile-time
// buffer via 2x unroll), register softmax, PV 2-term (Ph*Vh + Ph*Vl).
// ---------------------------------------------------------------------------
__global__ __launch_bounds__(256, 2) void attn_reg(
    const int* __restrict__ mask, float* __restrict__ out)
{
    __shared__ __half Ksh[2][32][72], Ksl[2][32][72];
    __shared__ __half Vsh[2][32][72], Vsl[2][32][72];
    __shared__ uint32_t mbw[2];

    const int tid = threadIdx.x, warp = tid >> 5, lane = tid & 31;
    const int g = lane >> 2, tg = lane & 3;
    const int b = blockIdx.z, h = blockIdx.y;
    const int q0 = blockIdx.x * 128;

    const int lrow = lane & 15, lcol8 = (lane >> 4) << 3;
    const int kvr  = (lane & 7) + ((lane >> 4) << 3);   // trans-ldmatrix row
    const int dcol = ((lane >> 3) & 1) * 8;
    const int cr = tid >> 3, cc = (tid & 7) * 8;

    // ---- Q fragments direct from pre-split gmem (pre-scaled by 1/8) ----
    unsigned qfh[4][4], qfl[4][4];
    {
        size_t r0 = (size_t)(b * LQ + q0 + warp * 16 + g) * (NH * DK) + h * DK;
        size_t r1 = r0 + (size_t)8 * (NH * DK);
#pragma unroll
        for (int kk = 0; kk < 4; ++kk) {
            int c = kk * 16 + 2 * tg;
            qfh[kk][0] = *(const uint32_t*)(g_qh + r0 + c);
            qfh[kk][1] = *(const uint32_t*)(g_qh + r1 + c);
            qfh[kk][2] = *(const uint32_t*)(g_qh + r0 + c + 8);
            qfh[kk][3] = *(const uint32_t*)(g_qh + r1 + c + 8);
            qfl[kk][0] = *(const uint32_t*)(g_ql + r0 + c);
            qfl[kk][1] = *(const uint32_t*)(g_ql + r1 + c);
            qfl[kk][2] = *(const uint32_t*)(g_ql + r0 + c + 8);
            qfl[kk][3] = *(const uint32_t*)(g_ql + r1 + c + 8);
        }
    }

    float o[8][4];
#pragma unroll
    for (int i = 0; i < 8; ++i)
#pragma unroll
        for (int j = 0; j < 4; ++j) o[i][j] = 0.f;
    float mrA = -INFINITY, mrB = -INFINITY, lrA = 0.f, lrB = 0.f;

    // ---- prime tile 0 into buffer 0 ----
    {
        size_t goff = (size_t)(b * LK + cr) * (NH * DK) + h * DK + cc;
        CP16(smem_u32(&Ksh[0][cr][cc]), g_kh + goff);
        CP16(smem_u32(&Ksl[0][cr][cc]), g_kl + goff);
        CP16(smem_u32(&Vsh[0][cr][cc]), g_vh + goff);
        CP16(smem_u32(&Vsl[0][cr][cc]), g_vl + goff);
        CPCOMMIT();
        if (warp == 0) {
            uint32_t bal = __ballot_sync(0xffffffffu, mask[b * LK + lane] != 0);
            if (lane == 0) mbw[0] = bal;
        }
    }

// One KV tile with compile-time buffer index BUF at position KT.
#define TILE_STEP(BUF, KT) do {                                               \
    CPWAIT0();                                                                \
    __syncthreads();                                                          \
    if ((KT) + 32 < LK) {                                                     \
        size_t goff = (size_t)(b * LK + (KT) + 32 + cr) * (NH * DK) + h * DK + cc; \
        CP16(smem_u32(&Ksh[(BUF) ^ 1][cr][cc]), g_kh + goff);                 \
        CP16(smem_u32(&Ksl[(BUF) ^ 1][cr][cc]), g_kl + goff);                 \
        CP16(smem_u32(&Vsh[(BUF) ^ 1][cr][cc]), g_vh + goff);                 \
        CP16(smem_u32(&Vsl[(BUF) ^ 1][cr][cc]), g_vl + goff);                 \
        CPCOMMIT();                                                           \
        if (warp == 0) {                                                      \
            uint32_t bal = __ballot_sync(0xffffffffu,                         \
                                mask[b * LK + (KT) + 32 + lane] != 0);        \
            if (lane == 0) mbw[(BUF) ^ 1] = bal;                              \
        }                                                                     \
    }                                                                         \
    const uint32_t mb = mbw[BUF];                                             \
    float sa[4][4];                                                           \
    _Pragma("unroll")                                                         \
    for (int nf = 0; nf < 4; ++nf)                                            \
        { sa[nf][0] = 0.f; sa[nf][1] = 0.f; sa[nf][2] = 0.f; sa[nf][3] = 0.f; } \
    _Pragma("unroll")                                                         \
    for (int kk = 0; kk < 4; ++kk) {                                          \
        _Pragma("unroll")                                                     \
        for (int nh = 0; nh < 2; ++nh) {                                      \
            unsigned kbh[4], kbl[4];                                          \
            uint32_t off = (uint32_t)((nh * 16 + lrow) * 72 + kk * 16 + lcol8) * 2; \
            ldm4(kbh, smem_u32(&Ksh[BUF][0][0]) + off);                       \
            ldm4(kbl, smem_u32(&Ksl[BUF][0][0]) + off);                       \
            _Pragma("unroll")                                                 \
            for (int j = 0; j < 2; ++j) {                                     \
                int nf = nh * 2 + j;                                          \
                mma16(sa[nf], qfh[kk], kbh[j], kbh[2 + j]);                   \
                mma16(sa[nf], qfl[kk], kbh[j], kbh[2 + j]);                   \
                mma16(sa[nf], qfh[kk], kbl[j], kbl[2 + j]);                   \
            }                                                                 \
        }                                                                     \
    }                                                                         \
    float mA = NEGV, mB = NEGV;                                               \
    _Pragma("unroll")                                                         \
    for (int nf = 0; nf < 4; ++nf) {                                          \
        int c0 = nf * 8 + 2 * tg;                                             \
        bool k0 = (mb >> c0) & 1u;                                            \
        bool k1 = (mb >> (c0 + 1)) & 1u;                                      \
        sa[nf][0] = k0 ? sa[nf][0] : NEGV;                                    \
        sa[nf][1] = k1 ? sa[nf][1] : NEGV;                                    \
        sa[nf][2] = k0 ? sa[nf][2] : NEGV;                                    \
        sa[nf][3] = k1 ? sa[nf][3] : NEGV;                                    \
        mA = fmaxf(mA, fmaxf(sa[nf][0], sa[nf][1]));                          \
        mB = fmaxf(mB, fmaxf(sa[nf][2], sa[nf][3]));                          \
    }                                                                         \
    mA = fmaxf(mA, __shfl_xor_sync(0xffffffffu, mA, 1));                      \
    mA = fmaxf(mA, __shfl_xor_sync(0xffffffffu, mA, 2));                      \
    mB = fmaxf(mB, __shfl_xor_sync(0xffffffffu, mB, 1));                      \
    mB = fmaxf(mB, __shfl_xor_sync(0xffffffffu, mB, 2));                      \
    float mnA = fmaxf(mrA, mA), mnB = fmaxf(mrB, mB);                         \
    float alA = __expf(mrA - mnA), alB = __expf(mrB - mnB);                   \
    mrA = mnA; mrB = mnB;                                                     \
    unsigned pah[2][4];                                                       \
    float lsA = 0.f, lsB = 0.f;                                               \
    _Pragma("unroll")                                                         \
    for (int jk = 0; jk < 2; ++jk) {                                          \
        _Pragma("unroll")                                                     \
        for (int t = 0; t < 2; ++t) {                                         \
            int nf = jk * 2 + t;                                              \
            float p0 = __expf(sa[nf][0] - mnA);                               \
            float p1 = __expf(sa[nf][1] - mnA);                               \
            float p2 = __expf(sa[nf][2] - mnB);                               \
            float p3 = __expf(sa[nf][3] - mnB);                               \
            lsA += p0 + p1; lsB += p2 + p3;                                   \
            pah[jk][2 * t]     = pack_h2(p0, p1);                             \
            pah[jk][2 * t + 1] = pack_h2(p2, p3);                             \
        }                                                                     \
    }                                                                         \
    lsA += __shfl_xor_sync(0xffffffffu, lsA, 1);                              \
    lsA += __shfl_xor_sync(0xffffffffu, lsA, 2);                              \
    lsB += __shfl_xor_sync(0xffffffffu, lsB, 1);                              \
    lsB += __shfl_xor_sync(0xffffffffu, lsB, 2);                              \
    lrA = lrA * alA + lsA;                                                    \
    lrB = lrB * alB + lsB;                                                    \
    _Pragma("unroll")                                                         \
    for (int nf = 0; nf < 8; ++nf) {                                          \
        o[nf][0] *= alA; o[nf][1] *= alA;                                     \
        o[nf][2] *= alB; o[nf][3] *= alB;                                     \
    }                                                                         \
    _Pragma("unroll")                                                         \
    for (int jk = 0; jk < 2; ++jk) {                                          \
        _Pragma("unroll")                                                     \
        for (int dh = 0; dh < 4; ++dh) {                                      \
            unsigned vbh[4], vbl[4];                                          \
            uint32_t off = (uint32_t)((jk * 16 + kvr) * 72 + dh * 16 + dcol) * 2; \
            ldm4t(vbh, smem_u32(&Vsh[BUF][0][0]) + off);                      \
            ldm4t(vbl, smem_u32(&Vsl[BUF][0][0]) + off);                      \
            _Pragma("unroll")                                                 \
            for (int j = 0; j < 2; ++j) {                                     \
                int nf = dh * 2 + j;                                          \
                mma16(o[nf], pah[jk], vbh[j], vbh[2 + j]);                    \
                mma16(o[nf], pah[jk], vbl[j], vbl[2 + j]);                    \
            }                                                                 \
        }                                                                     \
    }                                                                         \
} while (0)

    for (int kt = 0; kt < LK; kt += 64) {
        TILE_STEP(0, kt);
        TILE_STEP(1, kt + 32);
    }
#undef TILE_STEP

    // ---- normalize + store ----
    {
        float iA = 1.f / lrA, iB = 1.f / lrB;
        float* o0 = out + (size_t)(b * LQ + q0 + warp * 16 + g) * (NH * DK) + h * DK;
        float* o1 = o0 + (size_t)8 * (NH * DK);
#pragma unroll
        for (int nf = 0; nf < 8; ++nf) {
            int c = (nf >> 1) * 16 + (nf & 1) * 8 + 2 * tg;
            *(float2*)(o0 + c) = make_float2(o[nf][0] * iA, o[nf][1] * iA);
            *(float2*)(o1 + c) = make_float2(o[nf][2] * iB, o[nf][3] * iB);
        }
    }
}

// ---------------------------------------------------------------------------
extern "C" void kernel_launch(void* const* d_in, const int* in_sizes, int n_in,
                              void* d_out, int out_size)
{
    const float* Q    = (const float*)d_in[0];
    const float* K    = (const float*)d_in[1];
    const float* V    = (const float*)d_in[2];
    const int*   mask = (const int*)d_in[3];
    const float* Wq   = (const float*)d_in[4];
    const float* bq   = (const float*)d_in[5];
    const float* Wk   = (const float*)d_in[6];
    const float* Wv   = (const float*)d_in[7];
    const float* bv   = (const float*)d_in[8];
    float* out = (float*)d_out;

    dim3 gproj((NH * DK) / 64, (BB * LQ) / 128, 3);  // (16, 64, 3)
    proj_hmma<<<gproj, 256>>>(Q, K, V, Wq, bq, Wk, Wv, bv);

    dim3 gattn(LQ / 128, NH, BB);  // (16, 16, 4)
    attn_reg<<<gattn, 256>>>(mask, out);
}